// round 4
// baseline (speedup 1.0000x reference)
#include <cuda_runtime.h>
#include <math.h>

#define Bv 2
#define Lv 2048
#define Hv 16
#define DKv 64
#define DMv 1024
#define BHv (Bv*Hv)

// ---------------- scratch (static __device__ globals; no allocation) ----------
__device__ float g_Q[(size_t)BHv*Lv*DKv];
__device__ float g_K[(size_t)BHv*Lv*DKv];
__device__ float g_V[(size_t)BHv*Lv*DKv];
__device__ float g_ctx[(size_t)Bv*Lv*DMv];
__device__ float g_proj[(size_t)Bv*Lv*DMv];
// fallback attention buffer in case d_out only holds x (512 MB .bss)
__device__ float g_attn_fb[(size_t)BHv*Lv*Lv];

// ---------------- block reductions --------------------------------------------
__device__ __forceinline__ float blk_reduce_sum(float v, float* red) {
#pragma unroll
    for (int o = 16; o > 0; o >>= 1) v += __shfl_xor_sync(0xffffffffu, v, o);
    const int w = threadIdx.x >> 5;
    if ((threadIdx.x & 31) == 0) red[w] = v;
    __syncthreads();
    if (threadIdx.x < 32) {
        float t = (threadIdx.x < 8) ? red[threadIdx.x] : 0.f;
#pragma unroll
        for (int o = 4; o > 0; o >>= 1) t += __shfl_xor_sync(0xffffffffu, t, o);
        if (threadIdx.x == 0) red[0] = t;
    }
    __syncthreads();
    float r = red[0];
    __syncthreads();
    return r;
}

__device__ __forceinline__ float blk_reduce_max(float v, float* red) {
#pragma unroll
    for (int o = 16; o > 0; o >>= 1) v = fmaxf(v, __shfl_xor_sync(0xffffffffu, v, o));
    const int w = threadIdx.x >> 5;
    if ((threadIdx.x & 31) == 0) red[w] = v;
    __syncthreads();
    if (threadIdx.x < 32) {
        float t = (threadIdx.x < 8) ? red[threadIdx.x] : -INFINITY;
#pragma unroll
        for (int o = 4; o > 0; o >>= 1) t = fmaxf(t, __shfl_xor_sync(0xffffffffu, t, o));
        if (threadIdx.x == 0) red[0] = t;
    }
    __syncthreads();
    float r = red[0];
    __syncthreads();
    return r;
}

// ---------------- dense NT GEMM: C[m][n] = sum_k A[m,k]*B[n,k] ----------------
// M = 4096, N = 1024, K = 1024. 128x128 tile, 8x8 microtile, 256 threads.
// which: 0->g_Q, 1->g_K, 2->g_V (head-split layout), 3->A=g_ctx, C=g_proj (row-major)
__global__ void __launch_bounds__(256) gemm_nt128(const float* __restrict__ A,
                                                  const float* __restrict__ Bm,
                                                  int which)
{
    __shared__ float As[8][128];
    __shared__ float Bs[8][128];
    const int bm = blockIdx.y * 128;
    const int bn = blockIdx.x * 128;
    const int tid = threadIdx.x;
    const int lr = tid >> 1;
    const int lc = (tid & 1) << 2;
    const int tx = tid & 15;
    const int ty = tid >> 4;

    const float* Aeff = (which == 3) ? g_ctx : A;

    float acc[8][8];
#pragma unroll
    for (int i = 0; i < 8; ++i)
#pragma unroll
        for (int j = 0; j < 8; ++j) acc[i][j] = 0.f;

    const float* Ap = Aeff + (size_t)(bm + lr) * DMv + lc;
    const float* Bp = Bm  + (size_t)(bn + lr) * DMv + lc;

    for (int k0 = 0; k0 < DMv; k0 += 8) {
        float4 av = *(const float4*)(Ap + k0);
        float4 bv = *(const float4*)(Bp + k0);
        __syncthreads();
        As[lc+0][lr]=av.x; As[lc+1][lr]=av.y; As[lc+2][lr]=av.z; As[lc+3][lr]=av.w;
        Bs[lc+0][lr]=bv.x; Bs[lc+1][lr]=bv.y; Bs[lc+2][lr]=bv.z; Bs[lc+3][lr]=bv.w;
        __syncthreads();
#pragma unroll
        for (int kk = 0; kk < 8; ++kk) {
            float a[8], b[8];
#pragma unroll
            for (int i = 0; i < 8; ++i) a[i] = As[kk][ty*8 + i];
#pragma unroll
            for (int j = 0; j < 8; ++j) b[j] = Bs[kk][tx*8 + j];
#pragma unroll
            for (int i = 0; i < 8; ++i)
#pragma unroll
                for (int j = 0; j < 8; ++j) acc[i][j] = fmaf(a[i], b[j], acc[i][j]);
        }
    }

    float* C = (which == 0) ? g_Q : (which == 1) ? g_K : (which == 2) ? g_V : g_proj;
#pragma unroll
    for (int i = 0; i < 8; ++i) {
        const int m = bm + ty*8 + i;
#pragma unroll
        for (int j = 0; j < 8; ++j) {
            const int n = bn + tx*8 + j;
            size_t idx;
            if (which < 3) {
                const int b_ = m >> 11, l_ = m & (Lv-1);
                const int h_ = n >> 6,  d_ = n & (DKv-1);
                idx = (((size_t)(b_*Hv + h_))*Lv + l_)*DKv + d_;
            } else {
                idx = (size_t)m*DMv + n;
            }
            C[idx] = acc[i][j];
        }
    }
}

// ---------------- banded scores: S = Q K^T / 8 - bias (in-band only) ----------
__global__ void __launch_bounds__(256) scores_kernel(float* __restrict__ attn_arg,
    const float* __restrict__ scl_p, const float* __restrict__ tau_p,
    const int* __restrict__ ws_p)
{
    const int bh = blockIdx.z;
    const int q0 = blockIdx.y << 6;
    const int k0 = blockIdx.x << 6;
    const int hs = (*ws_p) >> 1;
    if (k0 > q0 + 63 + hs || k0 + 63 < q0 - hs) return;

    float* attn = attn_arg ? attn_arg : g_attn_fb;

    __shared__ float Qs[64][65];
    __shared__ float Ks[64][65];
    const int tid = threadIdx.x;
    const int r  = tid >> 2;
    const int c4 = (tid & 3) << 4;

    const float* qrow = g_Q + ((size_t)bh*Lv + q0 + r)*DKv + c4;
    const float* krow = g_K + ((size_t)bh*Lv + k0 + r)*DKv + c4;
#pragma unroll
    for (int u = 0; u < 16; u += 4) {
        float4 a = *(const float4*)(qrow + u);
        Qs[c4+u+0][r]=a.x; Qs[c4+u+1][r]=a.y; Qs[c4+u+2][r]=a.z; Qs[c4+u+3][r]=a.w;
        float4 c = *(const float4*)(krow + u);
        Ks[c4+u+0][r]=c.x; Ks[c4+u+1][r]=c.y; Ks[c4+u+2][r]=c.z; Ks[c4+u+3][r]=c.w;
    }
    __syncthreads();

    const int tx = tid & 15, ty = tid >> 4;
    float acc[4][4];
#pragma unroll
    for (int i = 0; i < 4; ++i)
#pragma unroll
        for (int j = 0; j < 4; ++j) acc[i][j] = 0.f;

#pragma unroll
    for (int kk = 0; kk < 64; ++kk) {
        float a[4], b[4];
#pragma unroll
        for (int i = 0; i < 4; ++i) a[i] = Qs[kk][(ty<<2)+i];
#pragma unroll
        for (int j = 0; j < 4; ++j) b[j] = Ks[kk][(tx<<2)+j];
#pragma unroll
        for (int i = 0; i < 4; ++i)
#pragma unroll
            for (int j = 0; j < 4; ++j) acc[i][j] = fmaf(a[i], b[j], acc[i][j]);
    }

    const float iscl = 1.f / (*scl_p);
    const float itau = 1.f / (*tau_p);
    float* base = attn + (size_t)bh*Lv*Lv;
#pragma unroll
    for (int i = 0; i < 4; ++i) {
        const int q = q0 + (ty<<2) + i;
#pragma unroll
        for (int j = 0; j < 4; ++j) {
            const int k = k0 + (tx<<2) + j;
            const int rel = q - k;
            if (rel <= hs && rel >= -hs) {
                const float bias = expf(-fabsf((float)rel * iscl) * itau);
                base[(size_t)q*Lv + k] = acc[i][j]*0.125f - bias;
            }
        }
    }
}

// ---------------- row softmax; writes full 2048-wide row (zeros outside band) --
__global__ void __launch_bounds__(256) softmax_kernel(float* __restrict__ attn_arg,
    const float* __restrict__ mask, const float* __restrict__ scl_p,
    const float* __restrict__ tau_p, const int* __restrict__ ws_p)
{
    const int q  = blockIdx.x;
    const int bh = blockIdx.y;
    const int b  = bh >> 4;
    const int tid = threadIdx.x;
    __shared__ float buf[Lv];
    __shared__ float red[32];

    float* attn = attn_arg ? attn_arg : g_attn_fb;
    const int hs = (*ws_p) >> 1;
    const float mval = mask[b*Lv + q];
    float* row = attn + ((size_t)bh*Lv + q)*Lv;

    int lo, hi;
    if (mval != 0.f) {
        lo = q - hs; if (lo < 0) lo = 0;
        hi = q + hs; if (hi > Lv-1) hi = Lv-1;
        for (int c = lo + tid; c <= hi; c += 256) buf[c - lo] = row[c];
    } else {
        // whole row is NEG - bias: softmax reduces to softmax(-bias) over all L
        lo = 0; hi = Lv-1;
        const float iscl = 1.f / (*scl_p);
        const float itau = 1.f / (*tau_p);
        for (int c = tid; c < Lv; c += 256)
            buf[c] = -expf(-fabsf((float)(q - c) * iscl) * itau);
    }
    __syncthreads();

    const int n = hi - lo + 1;
    float mx = -INFINITY;
    for (int i = tid; i < n; i += 256) mx = fmaxf(mx, buf[i]);
    mx = blk_reduce_max(mx, red);

    float s = 0.f;
    for (int i = tid; i < n; i += 256) { float e = expf(buf[i] - mx); buf[i] = e; s += e; }
    s = blk_reduce_sum(s, red);
    const float inv = 1.f / s;
    __syncthreads();

    for (int c = tid; c < Lv; c += 256) {
        float v = 0.f;
        if (c >= lo && c <= hi) v = buf[c - lo] * inv;
        row[c] = v;
    }
}

// ---------------- ctx = attn @ V (band-skip when tile fully unmasked) ---------
__global__ void __launch_bounds__(256) av_kernel(const float* __restrict__ attn_arg,
    const float* __restrict__ mask, const int* __restrict__ ws_p)
{
    const int q0 = blockIdx.x << 6;
    const int bh = blockIdx.y;
    const int b = bh >> 4, h = bh & 15;
    const int hs = (*ws_p) >> 1;
    const int tid = threadIdx.x;

    const float* attn = attn_arg ? attn_arg : g_attn_fb;

    __shared__ float Ps[64][65];   // [m][q]
    __shared__ float Vs[64][65];   // [m][d]
    __shared__ int s_all;
    if (tid == 0) s_all = 1;
    __syncthreads();
    if (tid < 64 && mask[b*Lv + q0 + tid] == 0.f) s_all = 0;
    __syncthreads();
    const int allm = s_all;

    const int r  = tid >> 2, c4 = (tid & 3) << 4;
    const int tx = tid & 15, ty = tid >> 4;
    float acc[4][4];
#pragma unroll
    for (int i = 0; i < 4; ++i)
#pragma unroll
        for (int j = 0; j < 4; ++j) acc[i][j] = 0.f;

    const float* abase = attn + (size_t)bh*Lv*Lv;
    for (int m0 = 0; m0 < Lv; m0 += 64) {
        // out-of-band attention probabilities are exactly 0 (safe to skip),
        // except masked rows where the full row is nonzero
        if (allm && (m0 > q0 + 63 + hs || m0 + 63 < q0 - hs)) continue;
        __syncthreads();
        const float* arow = abase + (size_t)(q0 + r)*Lv + m0 + c4;
#pragma unroll
        for (int u = 0; u < 16; u += 4) {
            float4 a = *(const float4*)(arow + u);
            Ps[c4+u+0][r]=a.x; Ps[c4+u+1][r]=a.y; Ps[c4+u+2][r]=a.z; Ps[c4+u+3][r]=a.w;
        }
        const float* vrow = g_V + ((size_t)bh*Lv + m0 + r)*DKv + c4;
#pragma unroll
        for (int u = 0; u < 16; u += 4) {
            float4 a = *(const float4*)(vrow + u);
            Vs[r][c4+u+0]=a.x; Vs[r][c4+u+1]=a.y; Vs[r][c4+u+2]=a.z; Vs[r][c4+u+3]=a.w;
        }
        __syncthreads();
#pragma unroll
        for (int kk = 0; kk < 64; ++kk) {
            float a[4], bb[4];
#pragma unroll
            for (int i = 0; i < 4; ++i) a[i] = Ps[kk][(ty<<2)+i];
#pragma unroll
            for (int j = 0; j < 4; ++j) bb[j] = Vs[kk][(tx<<2)+j];
#pragma unroll
            for (int i = 0; i < 4; ++i)
#pragma unroll
                for (int j = 0; j < 4; ++j) acc[i][j] = fmaf(a[i], bb[j], acc[i][j]);
        }
    }

#pragma unroll
    for (int i = 0; i < 4; ++i) {
        const int qq = q0 + (ty<<2) + i;
#pragma unroll
        for (int j = 0; j < 4; ++j) {
            const int d = (tx<<2) + j;
            g_ctx[((size_t)b*Lv + qq)*DMv + h*DKv + d] = acc[i][j];
        }
    }
}

// ---------------- residual + LayerNorm ----------------------------------------
__global__ void __launch_bounds__(256) ln_kernel(const float* __restrict__ qin,
    const float* __restrict__ lnw, const float* __restrict__ lnb,
    float* __restrict__ out)
{
    const int m = blockIdx.x;
    const int tid = threadIdx.x;
    __shared__ float xs[DMv];
    __shared__ float red[32];

    float s = 0.f;
    for (int i = tid; i < DMv; i += 256) {
        float v = g_proj[(size_t)m*DMv + i] + qin[(size_t)m*DMv + i];
        xs[i] = v; s += v;
    }
    s = blk_reduce_sum(s, red);
    const float mean = s * (1.f/DMv);

    float vs = 0.f;
    for (int i = tid; i < DMv; i += 256) { float d = xs[i] - mean; vs += d*d; }
    vs = blk_reduce_sum(vs, red);
    const float inv = rsqrtf(vs * (1.f/DMv) + 1e-6f);

    for (int i = tid; i < DMv; i += 256)
        out[(size_t)m*DMv + i] = (xs[i] - mean) * inv * lnw[i] + lnb[i];
}

// ---------------- launcher ------------------------------------------------------
extern "C" void kernel_launch(void* const* d_in, const int* in_sizes, int n_in,
                              void* d_out, int out_size)
{
    const float* q    = (const float*)d_in[0];
    const float* k    = (const float*)d_in[1];
    const float* v    = (const float*)d_in[2];
    const float* mask = (const float*)d_in[3];
    const float* Wq   = (const float*)d_in[4];
    const float* Wk   = (const float*)d_in[5];
    const float* Wv   = (const float*)d_in[6];
    const float* Wo   = (const float*)d_in[7];
    const float* scl  = (const float*)d_in[8];
    const float* tau  = (const float*)d_in[9];
    const float* lnw  = (const float*)d_in[10];
    const float* lnb  = (const float*)d_in[11];
    const int*   ws   = (const int*)d_in[12];   // int64 LE low word also reads OK
    (void)in_sizes; (void)n_in;

    float* xout = (float*)d_out;
    const long long XN = (long long)Bv*Lv*DMv;            // 4,194,304
    const long long AN = (long long)BHv*Lv*Lv;            // 134,217,728
    // attention goes into d_out right after x if there is room; else static fallback
    float* attn_out = ((long long)out_size >= XN + AN) ? (xout + XN) : nullptr;

    const dim3 gg(DMv/128, (Bv*Lv)/128);                  // (8, 32)

    gemm_nt128<<<gg, 256>>>(q, Wq, 0);
    gemm_nt128<<<gg, 256>>>(k, Wk, 1);
    gemm_nt128<<<gg, 256>>>(v, Wv, 2);

    scores_kernel<<<dim3(Lv/64, Lv/64, BHv), 256>>>(attn_out, scl, tau, ws);
    softmax_kernel<<<dim3(Lv, BHv), 256>>>(attn_out, mask, scl, tau, ws);
    av_kernel<<<dim3(Lv/64, BHv), 256>>>(attn_out, mask, ws);

    gemm_nt128<<<gg, 256>>>(nullptr, Wo, 3);              // A = g_ctx internally
    ln_kernel<<<Bv*Lv, 256>>>(q, lnw, lnb, xout);
}

// round 5
// speedup vs baseline: 1.0006x; 1.0006x over previous
#include <cuda_runtime.h>
#include <math.h>

#define Bv 2
#define Lv 2048
#define Hv 16
#define DKv 64
#define DMv 1024
#define BHv (Bv*Hv)

// ---------------- scratch (static __device__ globals; no allocation) ----------
__device__ float g_Q[(size_t)BHv*Lv*DKv];
__device__ float g_K[(size_t)BHv*Lv*DKv];
__device__ float g_V[(size_t)BHv*Lv*DKv];
__device__ float g_ctx[(size_t)Bv*Lv*DMv];
__device__ float g_proj[(size_t)Bv*Lv*DMv];
// fallback attention buffer in case d_out only holds x (512 MB .bss)
__device__ float g_attn_fb[(size_t)BHv*Lv*Lv];

// ---------------- block reductions --------------------------------------------
__device__ __forceinline__ float blk_reduce_sum(float v, float* red) {
#pragma unroll
    for (int o = 16; o > 0; o >>= 1) v += __shfl_xor_sync(0xffffffffu, v, o);
    const int w = threadIdx.x >> 5;
    if ((threadIdx.x & 31) == 0) red[w] = v;
    __syncthreads();
    if (threadIdx.x < 32) {
        float t = (threadIdx.x < 8) ? red[threadIdx.x] : 0.f;
#pragma unroll
        for (int o = 4; o > 0; o >>= 1) t += __shfl_xor_sync(0xffffffffu, t, o);
        if (threadIdx.x == 0) red[0] = t;
    }
    __syncthreads();
    float r = red[0];
    __syncthreads();
    return r;
}

__device__ __forceinline__ float blk_reduce_max(float v, float* red) {
#pragma unroll
    for (int o = 16; o > 0; o >>= 1) v = fmaxf(v, __shfl_xor_sync(0xffffffffu, v, o));
    const int w = threadIdx.x >> 5;
    if ((threadIdx.x & 31) == 0) red[w] = v;
    __syncthreads();
    if (threadIdx.x < 32) {
        float t = (threadIdx.x < 8) ? red[threadIdx.x] : -INFINITY;
#pragma unroll
        for (int o = 4; o > 0; o >>= 1) t = fmaxf(t, __shfl_xor_sync(0xffffffffu, t, o));
        if (threadIdx.x == 0) red[0] = t;
    }
    __syncthreads();
    float r = red[0];
    __syncthreads();
    return r;
}

// ---------------- dense NT GEMM: C[m][n] = sum_k A[m,k]*B[n,k] ----------------
// M = 4096, N = 1024, K = 1024. 128x128 tile, 8x8 microtile, 256 threads.
// which: 0->g_Q, 1->g_K, 2->g_V (head-split layout), 3->A=g_ctx, C=g_proj (row-major)
__global__ void __launch_bounds__(256) gemm_nt128(const float* __restrict__ A,
                                                  const float* __restrict__ Bm,
                                                  int which)
{
    __shared__ float As[8][128];
    __shared__ float Bs[8][128];
    const int bm = blockIdx.y * 128;
    const int bn = blockIdx.x * 128;
    const int tid = threadIdx.x;
    const int lr = tid >> 1;
    const int lc = (tid & 1) << 2;
    const int tx = tid & 15;
    const int ty = tid >> 4;

    const float* Aeff = (which == 3) ? g_ctx : A;

    float acc[8][8];
#pragma unroll
    for (int i = 0; i < 8; ++i)
#pragma unroll
        for (int j = 0; j < 8; ++j) acc[i][j] = 0.f;

    const float* Ap = Aeff + (size_t)(bm + lr) * DMv + lc;
    const float* Bp = Bm  + (size_t)(bn + lr) * DMv + lc;

    for (int k0 = 0; k0 < DMv; k0 += 8) {
        float4 av = *(const float4*)(Ap + k0);
        float4 bv = *(const float4*)(Bp + k0);
        __syncthreads();
        As[lc+0][lr]=av.x; As[lc+1][lr]=av.y; As[lc+2][lr]=av.z; As[lc+3][lr]=av.w;
        Bs[lc+0][lr]=bv.x; Bs[lc+1][lr]=bv.y; Bs[lc+2][lr]=bv.z; Bs[lc+3][lr]=bv.w;
        __syncthreads();
#pragma unroll
        for (int kk = 0; kk < 8; ++kk) {
            float a[8], b[8];
#pragma unroll
            for (int i = 0; i < 8; ++i) a[i] = As[kk][ty*8 + i];
#pragma unroll
            for (int j = 0; j < 8; ++j) b[j] = Bs[kk][tx*8 + j];
#pragma unroll
            for (int i = 0; i < 8; ++i)
#pragma unroll
                for (int j = 0; j < 8; ++j) acc[i][j] = fmaf(a[i], b[j], acc[i][j]);
        }
    }

    float* C = (which == 0) ? g_Q : (which == 1) ? g_K : (which == 2) ? g_V : g_proj;
#pragma unroll
    for (int i = 0; i < 8; ++i) {
        const int m = bm + ty*8 + i;
#pragma unroll
        for (int j = 0; j < 8; ++j) {
            const int n = bn + tx*8 + j;
            size_t idx;
            if (which < 3) {
                const int b_ = m >> 11, l_ = m & (Lv-1);
                const int h_ = n >> 6,  d_ = n & (DKv-1);
                idx = (((size_t)(b_*Hv + h_))*Lv + l_)*DKv + d_;
            } else {
                idx = (size_t)m*DMv + n;
            }
            C[idx] = acc[i][j];
        }
    }
}

// ---------------- banded scores: S = Q K^T / 8 - bias (in-band only) ----------
__global__ void __launch_bounds__(256) scores_kernel(float* __restrict__ attn_arg,
    const float* __restrict__ scl_p, const float* __restrict__ tau_p,
    const int* __restrict__ ws_p)
{
    const int bh = blockIdx.z;
    const int q0 = blockIdx.y << 6;
    const int k0 = blockIdx.x << 6;
    const int hs = (*ws_p) >> 1;
    if (k0 > q0 + 63 + hs || k0 + 63 < q0 - hs) return;

    float* attn = attn_arg ? attn_arg : g_attn_fb;

    __shared__ float Qs[64][65];
    __shared__ float Ks[64][65];
    const int tid = threadIdx.x;
    const int r  = tid >> 2;
    const int c4 = (tid & 3) << 4;

    const float* qrow = g_Q + ((size_t)bh*Lv + q0 + r)*DKv + c4;
    const float* krow = g_K + ((size_t)bh*Lv + k0 + r)*DKv + c4;
#pragma unroll
    for (int u = 0; u < 16; u += 4) {
        float4 a = *(const float4*)(qrow + u);
        Qs[c4+u+0][r]=a.x; Qs[c4+u+1][r]=a.y; Qs[c4+u+2][r]=a.z; Qs[c4+u+3][r]=a.w;
        float4 c = *(const float4*)(krow + u);
        Ks[c4+u+0][r]=c.x; Ks[c4+u+1][r]=c.y; Ks[c4+u+2][r]=c.z; Ks[c4+u+3][r]=c.w;
    }
    __syncthreads();

    const int tx = tid & 15, ty = tid >> 4;
    float acc[4][4];
#pragma unroll
    for (int i = 0; i < 4; ++i)
#pragma unroll
        for (int j = 0; j < 4; ++j) acc[i][j] = 0.f;

#pragma unroll
    for (int kk = 0; kk < 64; ++kk) {
        float a[4], b[4];
#pragma unroll
        for (int i = 0; i < 4; ++i) a[i] = Qs[kk][(ty<<2)+i];
#pragma unroll
        for (int j = 0; j < 4; ++j) b[j] = Ks[kk][(tx<<2)+j];
#pragma unroll
        for (int i = 0; i < 4; ++i)
#pragma unroll
            for (int j = 0; j < 4; ++j) acc[i][j] = fmaf(a[i], b[j], acc[i][j]);
    }

    const float iscl = 1.f / (*scl_p);
    const float itau = 1.f / (*tau_p);
    float* base = attn + (size_t)bh*Lv*Lv;
#pragma unroll
    for (int i = 0; i < 4; ++i) {
        const int q = q0 + (ty<<2) + i;
#pragma unroll
        for (int j = 0; j < 4; ++j) {
            const int k = k0 + (tx<<2) + j;
            const int rel = q - k;
            if (rel <= hs && rel >= -hs) {
                const float bias = expf(-fabsf((float)rel * iscl) * itau);
                base[(size_t)q*Lv + k] = acc[i][j]*0.125f - bias;
            }
        }
    }
}

// ---------------- row softmax; writes full 2048-wide row (zeros outside band) --
__global__ void __launch_bounds__(256) softmax_kernel(float* __restrict__ attn_arg,
    const float* __restrict__ mask, const float* __restrict__ scl_p,
    const float* __restrict__ tau_p, const int* __restrict__ ws_p)
{
    const int q  = blockIdx.x;
    const int bh = blockIdx.y;
    const int b  = bh >> 4;
    const int tid = threadIdx.x;
    __shared__ float buf[Lv];
    __shared__ float red[32];

    float* attn = attn_arg ? attn_arg : g_attn_fb;
    const int hs = (*ws_p) >> 1;
    const float mval = mask[b*Lv + q];
    float* row = attn + ((size_t)bh*Lv + q)*Lv;

    int lo, hi;
    if (mval != 0.f) {
        lo = q - hs; if (lo < 0) lo = 0;
        hi = q + hs; if (hi > Lv-1) hi = Lv-1;
        for (int c = lo + tid; c <= hi; c += 256) buf[c - lo] = row[c];
    } else {
        // whole row is NEG - bias: softmax reduces to softmax(-bias) over all L
        lo = 0; hi = Lv-1;
        const float iscl = 1.f / (*scl_p);
        const float itau = 1.f / (*tau_p);
        for (int c = tid; c < Lv; c += 256)
            buf[c] = -expf(-fabsf((float)(q - c) * iscl) * itau);
    }
    __syncthreads();

    const int n = hi - lo + 1;
    float mx = -INFINITY;
    for (int i = tid; i < n; i += 256) mx = fmaxf(mx, buf[i]);
    mx = blk_reduce_max(mx, red);

    float s = 0.f;
    for (int i = tid; i < n; i += 256) { float e = expf(buf[i] - mx); buf[i] = e; s += e; }
    s = blk_reduce_sum(s, red);
    const float inv = 1.f / s;
    __syncthreads();

    for (int c = tid; c < Lv; c += 256) {
        float v = 0.f;
        if (c >= lo && c <= hi) v = buf[c - lo] * inv;
        row[c] = v;
    }
}

// ---------------- ctx = attn @ V (band-skip when tile fully unmasked) ---------
__global__ void __launch_bounds__(256) av_kernel(const float* __restrict__ attn_arg,
    const float* __restrict__ mask, const int* __restrict__ ws_p)
{
    const int q0 = blockIdx.x << 6;
    const int bh = blockIdx.y;
    const int b = bh >> 4, h = bh & 15;
    const int hs = (*ws_p) >> 1;
    const int tid = threadIdx.x;

    const float* attn = attn_arg ? attn_arg : g_attn_fb;

    __shared__ float Ps[64][65];   // [m][q]
    __shared__ float Vs[64][65];   // [m][d]
    __shared__ int s_all;
    if (tid == 0) s_all = 1;
    __syncthreads();
    if (tid < 64 && mask[b*Lv + q0 + tid] == 0.f) s_all = 0;
    __syncthreads();
    const int allm = s_all;

    const int r  = tid >> 2, c4 = (tid & 3) << 4;
    const int tx = tid & 15, ty = tid >> 4;
    float acc[4][4];
#pragma unroll
    for (int i = 0; i < 4; ++i)
#pragma unroll
        for (int j = 0; j < 4; ++j) acc[i][j] = 0.f;

    const float* abase = attn + (size_t)bh*Lv*Lv;
    for (int m0 = 0; m0 < Lv; m0 += 64) {
        // out-of-band attention probabilities are exactly 0 (safe to skip),
        // except masked rows where the full row is nonzero
        if (allm && (m0 > q0 + 63 + hs || m0 + 63 < q0 - hs)) continue;
        __syncthreads();
        const float* arow = abase + (size_t)(q0 + r)*Lv + m0 + c4;
#pragma unroll
        for (int u = 0; u < 16; u += 4) {
            float4 a = *(const float4*)(arow + u);
            Ps[c4+u+0][r]=a.x; Ps[c4+u+1][r]=a.y; Ps[c4+u+2][r]=a.z; Ps[c4+u+3][r]=a.w;
        }
        const float* vrow = g_V + ((size_t)bh*Lv + m0 + r)*DKv + c4;
#pragma unroll
        for (int u = 0; u < 16; u += 4) {
            float4 a = *(const float4*)(vrow + u);
            Vs[r][c4+u+0]=a.x; Vs[r][c4+u+1]=a.y; Vs[r][c4+u+2]=a.z; Vs[r][c4+u+3]=a.w;
        }
        __syncthreads();
#pragma unroll
        for (int kk = 0; kk < 64; ++kk) {
            float a[4], bb[4];
#pragma unroll
            for (int i = 0; i < 4; ++i) a[i] = Ps[kk][(ty<<2)+i];
#pragma unroll
            for (int j = 0; j < 4; ++j) bb[j] = Vs[kk][(tx<<2)+j];
#pragma unroll
            for (int i = 0; i < 4; ++i)
#pragma unroll
                for (int j = 0; j < 4; ++j) acc[i][j] = fmaf(a[i], bb[j], acc[i][j]);
        }
    }

#pragma unroll
    for (int i = 0; i < 4; ++i) {
        const int qq = q0 + (ty<<2) + i;
#pragma unroll
        for (int j = 0; j < 4; ++j) {
            const int d = (tx<<2) + j;
            g_ctx[((size_t)b*Lv + qq)*DMv + h*DKv + d] = acc[i][j];
        }
    }
}

// ---------------- residual + LayerNorm ----------------------------------------
__global__ void __launch_bounds__(256) ln_kernel(const float* __restrict__ qin,
    const float* __restrict__ lnw, const float* __restrict__ lnb,
    float* __restrict__ out)
{
    const int m = blockIdx.x;
    const int tid = threadIdx.x;
    __shared__ float xs[DMv];
    __shared__ float red[32];

    float s = 0.f;
    for (int i = tid; i < DMv; i += 256) {
        float v = g_proj[(size_t)m*DMv + i] + qin[(size_t)m*DMv + i];
        xs[i] = v; s += v;
    }
    s = blk_reduce_sum(s, red);
    const float mean = s * (1.f/DMv);

    float vs = 0.f;
    for (int i = tid; i < DMv; i += 256) { float d = xs[i] - mean; vs += d*d; }
    vs = blk_reduce_sum(vs, red);
    const float inv = rsqrtf(vs * (1.f/DMv) + 1e-6f);

    for (int i = tid; i < DMv; i += 256)
        out[(size_t)m*DMv + i] = (xs[i] - mean) * inv * lnw[i] + lnb[i];
}

// ---------------- launcher ------------------------------------------------------
extern "C" void kernel_launch(void* const* d_in, const int* in_sizes, int n_in,
                              void* d_out, int out_size)
{
    const float* q    = (const float*)d_in[0];
    const float* k    = (const float*)d_in[1];
    const float* v    = (const float*)d_in[2];
    const float* mask = (const float*)d_in[3];
    const float* Wq   = (const float*)d_in[4];
    const float* Wk   = (const float*)d_in[5];
    const float* Wv   = (const float*)d_in[6];
    const float* Wo   = (const float*)d_in[7];
    const float* scl  = (const float*)d_in[8];
    const float* tau  = (const float*)d_in[9];
    const float* lnw  = (const float*)d_in[10];
    const float* lnb  = (const float*)d_in[11];
    const int*   ws   = (const int*)d_in[12];   // int64 LE low word also reads OK
    (void)in_sizes; (void)n_in;

    float* xout = (float*)d_out;
    const long long XN = (long long)Bv*Lv*DMv;            // 4,194,304
    const long long AN = (long long)BHv*Lv*Lv;            // 134,217,728
    // attention goes into d_out right after x if there is room; else static fallback
    float* attn_out = ((long long)out_size >= XN + AN) ? (xout + XN) : nullptr;

    const dim3 gg(DMv/128, (Bv*Lv)/128);                  // (8, 32)

    gemm_nt128<<<gg, 256>>>(q, Wq, 0);
    gemm_nt128<<<gg, 256>>>(k, Wk, 1);
    gemm_nt128<<<gg, 256>>>(v, Wv, 2);

    scores_kernel<<<dim3(Lv/64, Lv/64, BHv), 256>>>(attn_out, scl, tau, ws);
    softmax_kernel<<<dim3(Lv, BHv), 256>>>(attn_out, mask, scl, tau, ws);
    av_kernel<<<dim3(Lv/64, BHv), 256>>>(attn_out, mask, ws);

    gemm_nt128<<<gg, 256>>>(nullptr, Wo, 3);              // A = g_ctx internally
    ln_kernel<<<Bv*Lv, 256>>>(q, lnw, lnb, xout);
}

// round 7
// speedup vs baseline: 1.5448x; 1.5438x over previous
#include <cuda_runtime.h>
#include <cuda_bf16.h>
#include <math.h>
#include <stdint.h>

#define Bv 2
#define Lv 2048
#define Hv 16
#define DKv 64
#define DMv 1024
#define BHv (Bv*Hv)
#define Mv  (Bv*Lv)    // 4096

// ---------------- scratch (static __device__ globals; no allocation) ----------
__device__ __align__(16) float g_Q[(size_t)BHv*Lv*DKv];
__device__ __align__(16) float g_K[(size_t)BHv*Lv*DKv];
__device__ __align__(16) float g_V[(size_t)BHv*Lv*DKv];
__device__ __align__(16) float g_ctx[(size_t)Bv*Lv*DMv];
__device__ __align__(16) float g_proj[(size_t)Bv*Lv*DMv];
__device__ __align__(16) float g_attn_fb[(size_t)BHv*Lv*Lv];   // fallback if d_out lacks attention
// split-bf16 operand buffers for the tensor-core GEMMs
__device__ __align__(16) __nv_bfloat16 g_Ah[(size_t)Mv*DMv];
__device__ __align__(16) __nv_bfloat16 g_Al[(size_t)Mv*DMv];
__device__ __align__(16) __nv_bfloat16 g_Bh[(size_t)DMv*DMv];
__device__ __align__(16) __nv_bfloat16 g_Bl[(size_t)DMv*DMv];
__device__ float g_bias_lut[Lv];

// ================= helpers ======================================================
__device__ __forceinline__ uint32_t smem_u32(const void* p) {
    uint32_t a;
    asm("{ .reg .u64 t; cvta.to.shared.u64 t, %1; cvt.u32.u64 %0, t; }" : "=r"(a) : "l"(p));
    return a;
}
__device__ __forceinline__ void cp_async16(uint32_t dst, const void* src) {
    asm volatile("cp.async.cg.shared.global [%0], [%1], 16;\n" :: "r"(dst), "l"(src) : "memory");
}
__device__ __forceinline__ void mma_bf16(float* d, const uint32_t* a, const uint32_t* b) {
    asm volatile(
        "mma.sync.aligned.m16n8k16.row.col.f32.bf16.bf16.f32 "
        "{%0,%1,%2,%3}, {%4,%5,%6,%7}, {%8,%9}, {%0,%1,%2,%3};"
        : "+f"(d[0]), "+f"(d[1]), "+f"(d[2]), "+f"(d[3])
        : "r"(a[0]), "r"(a[1]), "r"(a[2]), "r"(a[3]), "r"(b[0]), "r"(b[1]));
}

// ---------------- block reductions --------------------------------------------
__device__ __forceinline__ float blk_reduce_sum(float v, float* red) {
#pragma unroll
    for (int o = 16; o > 0; o >>= 1) v += __shfl_xor_sync(0xffffffffu, v, o);
    const int w = threadIdx.x >> 5;
    if ((threadIdx.x & 31) == 0) red[w] = v;
    __syncthreads();
    if (threadIdx.x < 32) {
        float t = (threadIdx.x < 8) ? red[threadIdx.x] : 0.f;
#pragma unroll
        for (int o = 4; o > 0; o >>= 1) t += __shfl_xor_sync(0xffffffffu, t, o);
        if (threadIdx.x == 0) red[0] = t;
    }
    __syncthreads();
    float r = red[0];
    __syncthreads();
    return r;
}
__device__ __forceinline__ float blk_reduce_max(float v, float* red) {
#pragma unroll
    for (int o = 16; o > 0; o >>= 1) v = fmaxf(v, __shfl_xor_sync(0xffffffffu, v, o));
    const int w = threadIdx.x >> 5;
    if ((threadIdx.x & 31) == 0) red[w] = v;
    __syncthreads();
    if (threadIdx.x < 32) {
        float t = (threadIdx.x < 8) ? red[threadIdx.x] : -INFINITY;
#pragma unroll
        for (int o = 4; o > 0; o >>= 1) t = fmaxf(t, __shfl_xor_sync(0xffffffffu, t, o));
        if (threadIdx.x == 0) red[0] = t;
    }
    __syncthreads();
    float r = red[0];
    __syncthreads();
    return r;
}

// ---------------- bias LUT -----------------------------------------------------
__global__ void __launch_bounds__(256) bias_lut_kernel(const float* __restrict__ scl_p,
                                                       const float* __restrict__ tau_p) {
    const int i = blockIdx.x * 256 + threadIdx.x;
    if (i < Lv) g_bias_lut[i] = expf(-fabsf((float)i / (*scl_p)) / (*tau_p));
}

// ---------------- fp32 -> (hi, lo) bf16 split ----------------------------------
__global__ void __launch_bounds__(256) split_kernel(const float* __restrict__ src,
                                                    int isB, int n4, int useCtx) {
    const int i = blockIdx.x * 256 + threadIdx.x;
    if (i >= n4) return;
    const float4* s4 = (const float4*)(useCtx ? (const float*)g_ctx : src);
    const float4 v = s4[i];
    __nv_bfloat16* hi = isB ? g_Bh : g_Ah;
    __nv_bfloat16* lo = isB ? g_Bl : g_Al;
    float x[4] = {v.x, v.y, v.z, v.w};
    unsigned short hs[4], ls[4];
#pragma unroll
    for (int j = 0; j < 4; ++j) {
        __nv_bfloat16 h = __float2bfloat16_rn(x[j]);
        float r = x[j] - __bfloat162float(h);
        __nv_bfloat16 l = __float2bfloat16_rn(r);
        hs[j] = *(unsigned short*)&h;
        ls[j] = *(unsigned short*)&l;
    }
    ushort4 hv; hv.x = hs[0]; hv.y = hs[1]; hv.z = hs[2]; hv.w = hs[3];
    ushort4 lv; lv.x = ls[0]; lv.y = ls[1]; lv.z = ls[2]; lv.w = ls[3];
    *(ushort4*)(hi + (size_t)i * 4) = hv;
    *(ushort4*)(lo + (size_t)i * 4) = lv;
}

// ---------------- split-bf16 HMMA NT GEMM ---------------------------------------
// C[m][n] = sum_k A[m,k]*B[n,k]; M=4096, N=1024, K=1024.
// (Ah+Al)(Bh+Bl) ~= AhBh + AhBl + AlBh.  128x128 CTA tile, 8 warps of 64x32,
// K chunks of 32 double-buffered via cp.async. STR=40 is LDS-conflict-free for
// the 32-bit fragment-load pattern (row step 80B = 20 banks).
#define STR 40
#define TILE_ELE (128*STR)

__global__ void __launch_bounds__(256) tc_gemm(int which)
{
    extern __shared__ __align__(16) __nv_bfloat16 sm[];
    const int tid = threadIdx.x;
    const int wid = tid >> 5;
    const int lane = tid & 31;
    const int bn = blockIdx.x * 128;
    const int bm = blockIdx.y * 128;
    const int wm = (wid >> 2) * 64;    // 0 / 64
    const int wn = (wid & 3) * 32;     // 0 / 32 / 64 / 96
    const int r0 = lane >> 2;
    const int cq = (lane & 3) * 2;

    float acc[4][4][4];
#pragma unroll
    for (int mi = 0; mi < 4; ++mi)
#pragma unroll
        for (int ni = 0; ni < 4; ++ni)
#pragma unroll
            for (int r = 0; r < 4; ++r) acc[mi][ni][r] = 0.f;

    const uint32_t smb = smem_u32(sm);

    // load one K-chunk (32 cols) of Ah/Al/Bh/Bl into stage buffer
    auto load_chunk = [&](int c, int stage) {
        const uint32_t sb = smb + (uint32_t)stage * (4u * TILE_ELE * 2u);
#pragma unroll
        for (int it = 0; it < 8; ++it) {
            const int sg = tid + it * 256;            // 0..2047
            const int t  = sg >> 9;                   // tile 0..3
            const int u  = sg & 511;
            const int row = u >> 2;                   // 0..127
            const int c16 = u & 3;                    // 16B chunk within 64B row
            const char* gb = (t == 0) ? (const char*)g_Ah :
                             (t == 1) ? (const char*)g_Al :
                             (t == 2) ? (const char*)g_Bh : (const char*)g_Bl;
            const int rb = (t < 2) ? bm : bn;
            const char* src = gb + (size_t)(rb + row) * (DMv * 2) + (size_t)c * 64 + c16 * 16;
            const uint32_t dst = sb + (uint32_t)t * (TILE_ELE * 2u)
                               + (uint32_t)(row * STR + c16 * 8) * 2u;
            cp_async16(dst, src);
        }
        asm volatile("cp.async.commit_group;\n" ::: "memory");
    };

    load_chunk(0, 0);

    for (int c = 0; c < 32; ++c) {
        const int buf = c & 1;
        asm volatile("cp.async.wait_group 0;\n" ::: "memory");
        __syncthreads();
        if (c + 1 < 32) load_chunk(c + 1, buf ^ 1);

        const __nv_bfloat16* Ah = sm + (size_t)(buf * 4 + 0) * TILE_ELE;
        const __nv_bfloat16* Al = sm + (size_t)(buf * 4 + 1) * TILE_ELE;
        const __nv_bfloat16* Bh = sm + (size_t)(buf * 4 + 2) * TILE_ELE;
        const __nv_bfloat16* Bl = sm + (size_t)(buf * 4 + 3) * TILE_ELE;

#pragma unroll
        for (int ks = 0; ks < 2; ++ks) {
            const int kb = ks * 16;
            uint32_t aH[4][4], aL[4][4], bH[4][2], bL[4][2];
#pragma unroll
            for (int mi = 0; mi < 4; ++mi) {
                const int off = (wm + mi * 16 + r0) * STR + kb + cq;
                aH[mi][0] = *(const uint32_t*)(Ah + off);
                aH[mi][1] = *(const uint32_t*)(Ah + off + 8 * STR);
                aH[mi][2] = *(const uint32_t*)(Ah + off + 8);
                aH[mi][3] = *(const uint32_t*)(Ah + off + 8 * STR + 8);
                aL[mi][0] = *(const uint32_t*)(Al + off);
                aL[mi][1] = *(const uint32_t*)(Al + off + 8 * STR);
                aL[mi][2] = *(const uint32_t*)(Al + off + 8);
                aL[mi][3] = *(const uint32_t*)(Al + off + 8 * STR + 8);
            }
#pragma unroll
            for (int ni = 0; ni < 4; ++ni) {
                const int off = (wn + ni * 8 + r0) * STR + kb + cq;
                bH[ni][0] = *(const uint32_t*)(Bh + off);
                bH[ni][1] = *(const uint32_t*)(Bh + off + 8);
                bL[ni][0] = *(const uint32_t*)(Bl + off);
                bL[ni][1] = *(const uint32_t*)(Bl + off + 8);
            }
#pragma unroll
            for (int mi = 0; mi < 4; ++mi)
#pragma unroll
                for (int ni = 0; ni < 4; ++ni) {
                    mma_bf16(acc[mi][ni], aH[mi], bH[ni]);
                    mma_bf16(acc[mi][ni], aH[mi], bL[ni]);
                    mma_bf16(acc[mi][ni], aL[mi], bH[ni]);
                }
        }
        __syncthreads();
    }

    // epilogue: c0,c1 -> (m, n..n+1); c2,c3 -> (m+8, n..n+1)
#pragma unroll
    for (int mi = 0; mi < 4; ++mi) {
        const int m = bm + wm + mi * 16 + r0;
#pragma unroll
        for (int ni = 0; ni < 4; ++ni) {
            const int n = bn + wn + ni * 8 + cq;
#pragma unroll
            for (int half = 0; half < 2; ++half) {
                const int mm = m + half * 8;
                float2 val;
                val.x = acc[mi][ni][half * 2 + 0];
                val.y = acc[mi][ni][half * 2 + 1];
                if (which < 3) {
                    const int b_ = mm >> 11, l_ = mm & (Lv - 1);
                    const int h_ = n >> 6,  d_ = n & (DKv - 1);
                    float* C = (which == 0) ? g_Q : (which == 1) ? g_K : g_V;
                    *(float2*)&C[(((size_t)(b_ * Hv + h_)) * Lv + l_) * DKv + d_] = val;
                } else {
                    *(float2*)&g_proj[(size_t)mm * DMv + n] = val;
                }
            }
        }
    }
}

// ---------------- banded scores: 128x128 tiles, 8x8 quadrant microtile ---------
__global__ void __launch_bounds__(256) scores2_kernel(float* __restrict__ attn_arg,
                                                      const int* __restrict__ ws_p)
{
    const int bh = blockIdx.z;
    const int q0 = blockIdx.y << 7;
    const int k0 = blockIdx.x << 7;
    const int hs = (*ws_p) >> 1;
    if (k0 > q0 + 127 + hs || k0 + 127 < q0 - hs) return;
    float* attn = attn_arg ? attn_arg : g_attn_fb;

    extern __shared__ float smf[];          // Qs[64][128] then Ks[64][128]
    float* Qs = smf;
    float* Ks = smf + 64 * 128;

    const int tid = threadIdx.x;
    const float* qg = g_Q + ((size_t)bh * Lv + q0) * DKv;
    const float* kg = g_K + ((size_t)bh * Lv + k0) * DKv;
#pragma unroll
    for (int it = 0; it < 8; ++it) {
        const int f = tid + it * 256;
        const int row = f >> 4;
        const int c4  = (f & 15) << 2;
        const float4 a = *(const float4*)(qg + (size_t)row * DKv + c4);
        Qs[(c4+0)*128 + row] = a.x; Qs[(c4+1)*128 + row] = a.y;
        Qs[(c4+2)*128 + row] = a.z; Qs[(c4+3)*128 + row] = a.w;
        const float4 b = *(const float4*)(kg + (size_t)row * DKv + c4);
        Ks[(c4+0)*128 + row] = b.x; Ks[(c4+1)*128 + row] = b.y;
        Ks[(c4+2)*128 + row] = b.z; Ks[(c4+3)*128 + row] = b.w;
    }
    __syncthreads();

    const int tx = tid & 15, ty = tid >> 4;
    float acc[8][8];
#pragma unroll
    for (int i = 0; i < 8; ++i)
#pragma unroll
        for (int j = 0; j < 8; ++j) acc[i][j] = 0.f;

#pragma unroll
    for (int kk = 0; kk < 64; ++kk) {
        const float4 a0 = *(const float4*)&Qs[kk*128 + ty*4];
        const float4 a1 = *(const float4*)&Qs[kk*128 + 64 + ty*4];
        const float4 b0 = *(const float4*)&Ks[kk*128 + tx*4];
        const float4 b1 = *(const float4*)&Ks[kk*128 + 64 + tx*4];
        const float av[8] = {a0.x,a0.y,a0.z,a0.w,a1.x,a1.y,a1.z,a1.w};
        const float bv[8] = {b0.x,b0.y,b0.z,b0.w,b1.x,b1.y,b1.z,b1.w};
#pragma unroll
        for (int i = 0; i < 8; ++i)
#pragma unroll
            for (int j = 0; j < 8; ++j) acc[i][j] = fmaf(av[i], bv[j], acc[i][j]);
    }

    float* base = attn + (size_t)bh * Lv * Lv;
#pragma unroll
    for (int i = 0; i < 8; ++i) {
        const int q = q0 + ((i < 4) ? ty*4 + i : 64 + ty*4 + (i - 4));
        float* rowp = base + (size_t)q * Lv;
#pragma unroll
        for (int j = 0; j < 8; ++j) {
            const int k = k0 + ((j < 4) ? tx*4 + j : 64 + tx*4 + (j - 4));
            const int ar = abs(q - k);
            if (ar <= hs) rowp[k] = acc[i][j] * 0.125f - g_bias_lut[ar];
        }
    }
}

// ---------------- row softmax; full 2048-wide row (zeros outside band) ---------
__global__ void __launch_bounds__(256) softmax_kernel(float* __restrict__ attn_arg,
    const float* __restrict__ mask, const int* __restrict__ ws_p)
{
    const int q  = blockIdx.x;
    const int bh = blockIdx.y;
    const int b  = bh >> 4;
    const int tid = threadIdx.x;
    __shared__ float buf[Lv];
    __shared__ float red[32];

    float* attn = attn_arg ? attn_arg : g_attn_fb;
    const int hs = (*ws_p) >> 1;
    const float mval = mask[b * Lv + q];
    float* row = attn + ((size_t)bh * Lv + q) * Lv;

    int lo, hi;
    if (mval != 0.f) {
        lo = q - hs; if (lo < 0) lo = 0;
        hi = q + hs; if (hi > Lv - 1) hi = Lv - 1;
        for (int c = lo + tid; c <= hi; c += 256) buf[c - lo] = row[c];
    } else {
        lo = 0; hi = Lv - 1;
        for (int c = tid; c < Lv; c += 256) buf[c] = -g_bias_lut[abs(q - c)];
    }
    __syncthreads();

    const int n = hi - lo + 1;
    float mx = -INFINITY;
    for (int i = tid; i < n; i += 256) mx = fmaxf(mx, buf[i]);
    mx = blk_reduce_max(mx, red);

    float s = 0.f;
    for (int i = tid; i < n; i += 256) { const float e = expf(buf[i] - mx); buf[i] = e; s += e; }
    s = blk_reduce_sum(s, red);
    const float inv = 1.f / s;
    __syncthreads();

    for (int c4 = tid * 4; c4 < Lv; c4 += 1024) {
        float4 v;
        v.x = (c4+0 >= lo && c4+0 <= hi) ? buf[c4+0-lo] * inv : 0.f;
        v.y = (c4+1 >= lo && c4+1 <= hi) ? buf[c4+1-lo] * inv : 0.f;
        v.z = (c4+2 >= lo && c4+2 <= hi) ? buf[c4+2-lo] * inv : 0.f;
        v.w = (c4+3 >= lo && c4+3 <= hi) ? buf[c4+3-lo] * inv : 0.f;
        *(float4*)(row + c4) = v;
    }
}

// ---------------- ctx = attn @ V (band-skip when tile fully unmasked) ----------
__global__ void __launch_bounds__(256) av_kernel(const float* __restrict__ attn_arg,
    const float* __restrict__ mask, const int* __restrict__ ws_p)
{
    const int q0 = blockIdx.x << 6;
    const int bh = blockIdx.y;
    const int b = bh >> 4, h = bh & 15;
    const int hs = (*ws_p) >> 1;
    const int tid = threadIdx.x;

    const float* attn = attn_arg ? attn_arg : g_attn_fb;

    __shared__ float Ps[64][65];
    __shared__ float Vs[64][65];
    __shared__ int s_all;
    if (tid == 0) s_all = 1;
    __syncthreads();
    if (tid < 64 && mask[b * Lv + q0 + tid] == 0.f) s_all = 0;
    __syncthreads();
    const int allm = s_all;

    const int r  = tid >> 2, c4 = (tid & 3) << 4;
    const int tx = tid & 15, ty = tid >> 4;
    float acc[4][4];
#pragma unroll
    for (int i = 0; i < 4; ++i)
#pragma unroll
        for (int j = 0; j < 4; ++j) acc[i][j] = 0.f;

    const float* abase = attn + (size_t)bh * Lv * Lv;
    for (int m0 = 0; m0 < Lv; m0 += 64) {
        if (allm && (m0 > q0 + 63 + hs || m0 + 63 < q0 - hs)) continue;
        __syncthreads();
        const float* arow = abase + (size_t)(q0 + r) * Lv + m0 + c4;
#pragma unroll
        for (int u = 0; u < 16; u += 4) {
            const float4 a = *(const float4*)(arow + u);
            Ps[c4+u+0][r]=a.x; Ps[c4+u+1][r]=a.y; Ps[c4+u+2][r]=a.z; Ps[c4+u+3][r]=a.w;
        }
        const float* vrow = g_V + ((size_t)bh * Lv + m0 + r) * DKv + c4;
#pragma unroll
        for (int u = 0; u < 16; u += 4) {
            const float4 a = *(const float4*)(vrow + u);
            Vs[r][c4+u+0]=a.x; Vs[r][c4+u+1]=a.y; Vs[r][c4+u+2]=a.z; Vs[r][c4+u+3]=a.w;
        }
        __syncthreads();
#pragma unroll
        for (int kk = 0; kk < 64; ++kk) {
            float a[4], bb[4];
#pragma unroll
            for (int i = 0; i < 4; ++i) a[i] = Ps[kk][(ty<<2)+i];
#pragma unroll
            for (int j = 0; j < 4; ++j) bb[j] = Vs[kk][(tx<<2)+j];
#pragma unroll
            for (int i = 0; i < 4; ++i)
#pragma unroll
                for (int j = 0; j < 4; ++j) acc[i][j] = fmaf(a[i], bb[j], acc[i][j]);
        }
    }

#pragma unroll
    for (int i = 0; i < 4; ++i) {
        const int qq = q0 + (ty<<2) + i;
#pragma unroll
        for (int j = 0; j < 4; ++j) {
            const int d = (tx<<2) + j;
            g_ctx[((size_t)b * Lv + qq) * DMv + h * DKv + d] = acc[i][j];
        }
    }
}

// ---------------- residual + LayerNorm -----------------------------------------
__global__ void __launch_bounds__(256) ln_kernel(const float* __restrict__ qin,
    const float* __restrict__ lnw, const float* __restrict__ lnb,
    float* __restrict__ out)
{
    const int m = blockIdx.x;
    const int tid = threadIdx.x;
    __shared__ float xs[DMv];
    __shared__ float red[32];

    float s = 0.f;
    for (int i = tid; i < DMv; i += 256) {
        const float v = g_proj[(size_t)m * DMv + i] + qin[(size_t)m * DMv + i];
        xs[i] = v; s += v;
    }
    s = blk_reduce_sum(s, red);
    const float mean = s * (1.f / DMv);

    float vs = 0.f;
    for (int i = tid; i < DMv; i += 256) { const float d = xs[i] - mean; vs += d * d; }
    vs = blk_reduce_sum(vs, red);
    const float inv = rsqrtf(vs * (1.f / DMv) + 1e-6f);

    for (int i = tid; i < DMv; i += 256)
        out[(size_t)m * DMv + i] = (xs[i] - mean) * inv * lnw[i] + lnb[i];
}

// ---------------- launcher ------------------------------------------------------
extern "C" void kernel_launch(void* const* d_in, const int* in_sizes, int n_in,
                              void* d_out, int out_size)
{
    const float* q    = (const float*)d_in[0];
    const float* k    = (const float*)d_in[1];
    const float* v    = (const float*)d_in[2];
    const float* mask = (const float*)d_in[3];
    const float* Wq   = (const float*)d_in[4];
    const float* Wk   = (const float*)d_in[5];
    const float* Wv   = (const float*)d_in[6];
    const float* Wo   = (const float*)d_in[7];
    const float* scl  = (const float*)d_in[8];
    const float* tau  = (const float*)d_in[9];
    const float* lnw  = (const float*)d_in[10];
    const float* lnb  = (const float*)d_in[11];
    const int*   ws   = (const int*)d_in[12];
    (void)in_sizes; (void)n_in;

    const int gemm_smem = 2 * 4 * TILE_ELE * 2;   // 81920 B
    cudaFuncSetAttribute(tc_gemm, cudaFuncAttributeMaxDynamicSharedMemorySize, gemm_smem);
    cudaFuncSetAttribute(scores2_kernel, cudaFuncAttributeMaxDynamicSharedMemorySize, 65536);

    float* xout = (float*)d_out;
    const long long XN = (long long)Bv * Lv * DMv;
    const long long AN = (long long)BHv * Lv * Lv;
    float* attn_out = ((long long)out_size >= XN + AN) ? (xout + XN) : nullptr;

    const int A4 = Mv * DMv / 4;
    const int B4 = DMv * DMv / 4;
    const dim3 gg(DMv / 128, Mv / 128);   // (8, 32)

    bias_lut_kernel<<<8, 256>>>(scl, tau);

    split_kernel<<<A4 / 256, 256>>>(q,  0, A4, 0);
    split_kernel<<<B4 / 256, 256>>>(Wq, 1, B4, 0);
    tc_gemm<<<gg, 256, gemm_smem>>>(0);

    split_kernel<<<A4 / 256, 256>>>(k,  0, A4, 0);
    split_kernel<<<B4 / 256, 256>>>(Wk, 1, B4, 0);
    tc_gemm<<<gg, 256, gemm_smem>>>(1);

    split_kernel<<<A4 / 256, 256>>>(v,  0, A4, 0);
    split_kernel<<<B4 / 256, 256>>>(Wv, 1, B4, 0);
    tc_gemm<<<gg, 256, gemm_smem>>>(2);

    scores2_kernel<<<dim3(Lv/128, Lv/128, BHv), 256, 65536>>>(attn_out, ws);
    softmax_kernel<<<dim3(Lv, BHv), 256>>>(attn_out, mask, ws);
    av_kernel<<<dim3(Lv/64, BHv), 256>>>(attn_out, mask, ws);

    split_kernel<<<A4 / 256, 256>>>(nullptr, 0, A4, 1);   // A = g_ctx
    split_kernel<<<B4 / 256, 256>>>(Wo, 1, B4, 0);
    tc_gemm<<<gg, 256, gemm_smem>>>(3);

    ln_kernel<<<Mv, 256>>>(q, lnw, lnb, xout);
}

// round 8
// speedup vs baseline: 2.3532x; 1.5233x over previous
#include <cuda_runtime.h>
#include <cuda_bf16.h>
#include <math.h>
#include <stdint.h>

#define Bv 2
#define Lv 2048
#define Hv 16
#define DKv 64
#define DMv 1024
#define BHv (Bv*Hv)
#define Mv  (Bv*Lv)    // 4096

// ---------------- scratch (static __device__ globals; no allocation) ----------
__device__ __align__(16) float g_ctx[(size_t)Bv*Lv*DMv];
__device__ __align__(16) float g_proj[(size_t)Bv*Lv*DMv];
__device__ __align__(16) float g_attn_fb[(size_t)BHv*Lv*Lv];   // fallback if d_out lacks attention
// split-bf16 operand buffers for the dense GEMMs
__device__ __align__(16) __nv_bfloat16 g_Ah[(size_t)Mv*DMv];
__device__ __align__(16) __nv_bfloat16 g_Al[(size_t)Mv*DMv];
__device__ __align__(16) __nv_bfloat16 g_Bh[(size_t)DMv*DMv];
__device__ __align__(16) __nv_bfloat16 g_Bl[(size_t)DMv*DMv];
// split-bf16 Q/K (head-major [bh][L][64]) and transposed V ([bh][64][L])
__device__ __align__(16) __nv_bfloat16 g_Qh[(size_t)BHv*Lv*DKv];
__device__ __align__(16) __nv_bfloat16 g_Ql[(size_t)BHv*Lv*DKv];
__device__ __align__(16) __nv_bfloat16 g_Kh[(size_t)BHv*Lv*DKv];
__device__ __align__(16) __nv_bfloat16 g_Kl[(size_t)BHv*Lv*DKv];
__device__ __align__(16) __nv_bfloat16 g_Vth[(size_t)BHv*DKv*Lv];
__device__ __align__(16) __nv_bfloat16 g_Vtl[(size_t)BHv*DKv*Lv];
__device__ float g_bias_lut[Lv];

// ================= helpers ======================================================
__device__ __forceinline__ uint32_t smem_u32(const void* p) {
    uint32_t a;
    asm("{ .reg .u64 t; cvta.to.shared.u64 t, %1; cvt.u32.u64 %0, t; }" : "=r"(a) : "l"(p));
    return a;
}
__device__ __forceinline__ void cp_async16(uint32_t dst, const void* src) {
    asm volatile("cp.async.cg.shared.global [%0], [%1], 16;\n" :: "r"(dst), "l"(src) : "memory");
}
__device__ __forceinline__ void mma_bf16(float* d, const uint32_t* a, const uint32_t* b) {
    asm volatile(
        "mma.sync.aligned.m16n8k16.row.col.f32.bf16.bf16.f32 "
        "{%0,%1,%2,%3}, {%4,%5,%6,%7}, {%8,%9}, {%0,%1,%2,%3};"
        : "+f"(d[0]), "+f"(d[1]), "+f"(d[2]), "+f"(d[3])
        : "r"(a[0]), "r"(a[1]), "r"(a[2]), "r"(a[3]), "r"(b[0]), "r"(b[1]));
}
#define LDSM_X4(r0,r1,r2,r3,addr) \
    asm volatile("ldmatrix.sync.aligned.m8n8.x4.shared.b16 {%0,%1,%2,%3}, [%4];" \
        : "=r"(r0), "=r"(r1), "=r"(r2), "=r"(r3) : "r"(addr))

// ---------------- block reductions --------------------------------------------
__device__ __forceinline__ float blk_reduce_sum(float v, float* red) {
#pragma unroll
    for (int o = 16; o > 0; o >>= 1) v += __shfl_xor_sync(0xffffffffu, v, o);
    const int w = threadIdx.x >> 5;
    if ((threadIdx.x & 31) == 0) red[w] = v;
    __syncthreads();
    if (threadIdx.x < 32) {
        float t = (threadIdx.x < 8) ? red[threadIdx.x] : 0.f;
#pragma unroll
        for (int o = 4; o > 0; o >>= 1) t += __shfl_xor_sync(0xffffffffu, t, o);
        if (threadIdx.x == 0) red[0] = t;
    }
    __syncthreads();
    float r = red[0];
    __syncthreads();
    return r;
}
__device__ __forceinline__ float blk_reduce_max(float v, float* red) {
#pragma unroll
    for (int o = 16; o > 0; o >>= 1) v = fmaxf(v, __shfl_xor_sync(0xffffffffu, v, o));
    const int w = threadIdx.x >> 5;
    if ((threadIdx.x & 31) == 0) red[w] = v;
    __syncthreads();
    if (threadIdx.x < 32) {
        float t = (threadIdx.x < 8) ? red[threadIdx.x] : -INFINITY;
#pragma unroll
        for (int o = 4; o > 0; o >>= 1) t = fmaxf(t, __shfl_xor_sync(0xffffffffu, t, o));
        if (threadIdx.x == 0) red[0] = t;
    }
    __syncthreads();
    float r = red[0];
    __syncthreads();
    return r;
}

// ---------------- bias LUT -----------------------------------------------------
__global__ void __launch_bounds__(256) bias_lut_kernel(const float* __restrict__ scl_p,
                                                       const float* __restrict__ tau_p) {
    const int i = blockIdx.x * 256 + threadIdx.x;
    if (i < Lv) g_bias_lut[i] = expf(-fabsf((float)i / (*scl_p)) / (*tau_p));
}

// ---------------- fp32 -> (hi, lo) bf16 split ----------------------------------
__global__ void __launch_bounds__(256) split_kernel(const float* __restrict__ src,
                                                    int isB, int n4, int useCtx) {
    const int i = blockIdx.x * 256 + threadIdx.x;
    if (i >= n4) return;
    const float4* s4 = (const float4*)(useCtx ? (const float*)g_ctx : src);
    const float4 v = s4[i];
    __nv_bfloat16* hi = isB ? g_Bh : g_Ah;
    __nv_bfloat16* lo = isB ? g_Bl : g_Al;
    float x[4] = {v.x, v.y, v.z, v.w};
    unsigned short hs[4], ls[4];
#pragma unroll
    for (int j = 0; j < 4; ++j) {
        __nv_bfloat16 h = __float2bfloat16_rn(x[j]);
        float r = x[j] - __bfloat162float(h);
        __nv_bfloat16 l = __float2bfloat16_rn(r);
        hs[j] = __bfloat16_as_ushort(h);
        ls[j] = __bfloat16_as_ushort(l);
    }
    ushort4 hv; hv.x = hs[0]; hv.y = hs[1]; hv.z = hs[2]; hv.w = hs[3];
    ushort4 lv; lv.x = ls[0]; lv.y = ls[1]; lv.z = ls[2]; lv.w = ls[3];
    *(ushort4*)(hi + (size_t)i * 4) = hv;
    *(ushort4*)(lo + (size_t)i * 4) = lv;
}

// ---------------- split-bf16 HMMA NT GEMM ---------------------------------------
// C[m][n] = sum_k A[m,k]*B[n,k]; M=4096, N=1024, K=1024.
// (Ah+Al)(Bh+Bl) ~= AhBh + AhBl + AlBh.  128x128 CTA tile, 8 warps of 64x32,
// K chunks of 32 double-buffered via cp.async, ldmatrix fragment loads.
// which 0/1: write split-bf16 Q/K [bh][L][64]; which 2: write transposed split V;
// which 3: write fp32 g_proj.
#define STR 40
#define TILE_ELE (128*STR)
#define TILEB (TILE_ELE*2)

__global__ void __launch_bounds__(256) tc_gemm(int which)
{
    extern __shared__ __align__(16) __nv_bfloat16 sm[];
    const int tid = threadIdx.x;
    const int wid = tid >> 5;
    const int lane = tid & 31;
    const int bn = blockIdx.x * 128;
    const int bm = blockIdx.y * 128;
    const int wm = (wid >> 2) * 64;
    const int wn = (wid & 3) * 32;

    float acc[4][4][4];
#pragma unroll
    for (int mi = 0; mi < 4; ++mi)
#pragma unroll
        for (int ni = 0; ni < 4; ++ni)
#pragma unroll
            for (int r = 0; r < 4; ++r) acc[mi][ni][r] = 0.f;

    const uint32_t smb = smem_u32(sm);

    auto load_chunk = [&](int c, int stage) {
        const uint32_t sb = smb + (uint32_t)stage * (4u * TILEB);
#pragma unroll
        for (int it = 0; it < 8; ++it) {
            const int sg = tid + it * 256;            // 0..2047
            const int t  = sg >> 9;                   // tile 0..3
            const int u  = sg & 511;
            const int row = u >> 2;                   // 0..127
            const int c16 = u & 3;
            const char* gb = (t == 0) ? (const char*)g_Ah :
                             (t == 1) ? (const char*)g_Al :
                             (t == 2) ? (const char*)g_Bh : (const char*)g_Bl;
            const int rb = (t < 2) ? bm : bn;
            const char* src = gb + (size_t)(rb + row) * (DMv * 2) + (size_t)c * 64 + c16 * 16;
            const uint32_t dst = sb + (uint32_t)t * TILEB
                               + (uint32_t)(row * STR + c16 * 8) * 2u;
            cp_async16(dst, src);
        }
        asm volatile("cp.async.commit_group;\n" ::: "memory");
    };

    load_chunk(0, 0);

    for (int c = 0; c < 32; ++c) {
        const int buf = c & 1;
        asm volatile("cp.async.wait_group 0;\n" ::: "memory");
        __syncthreads();
        if (c + 1 < 32) load_chunk(c + 1, buf ^ 1);

        const uint32_t sb = smb + (uint32_t)buf * (4u * TILEB);

#pragma unroll
        for (int ks = 0; ks < 2; ++ks) {
            const int kb = ks * 16;
            uint32_t aH[4][4], aL[4][4], bH[4][2], bL[4][2];
            const uint32_t arow = (uint32_t)(((wm + (lane & 15)) * STR + kb + ((lane >> 4) << 3)) * 2);
#pragma unroll
            for (int mi = 0; mi < 4; ++mi) {
                const uint32_t ad = sb + arow + (uint32_t)(mi * 16 * STR * 2);
                LDSM_X4(aH[mi][0], aH[mi][1], aH[mi][2], aH[mi][3], ad);
                LDSM_X4(aL[mi][0], aL[mi][1], aL[mi][2], aL[mi][3], ad + TILEB);
            }
            const uint32_t brow = (uint32_t)((((wn + (lane & 7) + ((lane >> 4) << 3)) * STR)
                                 + kb + (((lane >> 3) & 1) << 3)) * 2);
#pragma unroll
            for (int np = 0; np < 2; ++np) {
                const uint32_t bd = sb + 2u * TILEB + brow + (uint32_t)(np * 16 * STR * 2);
                uint32_t r0, r1, r2, r3;
                LDSM_X4(r0, r1, r2, r3, bd);
                bH[np*2][0] = r0; bH[np*2][1] = r1; bH[np*2+1][0] = r2; bH[np*2+1][1] = r3;
                LDSM_X4(r0, r1, r2, r3, bd + TILEB);
                bL[np*2][0] = r0; bL[np*2][1] = r1; bL[np*2+1][0] = r2; bL[np*2+1][1] = r3;
            }
#pragma unroll
            for (int mi = 0; mi < 4; ++mi)
#pragma unroll
                for (int ni = 0; ni < 4; ++ni) {
                    mma_bf16(acc[mi][ni], aH[mi], bH[ni]);
                    mma_bf16(acc[mi][ni], aH[mi], bL[ni]);
                    mma_bf16(acc[mi][ni], aL[mi], bH[ni]);
                }
        }
        __syncthreads();
    }

    const int r0 = lane >> 2;
    const int cq = (lane & 3) * 2;
#pragma unroll
    for (int mi = 0; mi < 4; ++mi) {
        const int m = bm + wm + mi * 16 + r0;
#pragma unroll
        for (int ni = 0; ni < 4; ++ni) {
            const int n = bn + wn + ni * 8 + cq;
#pragma unroll
            for (int half = 0; half < 2; ++half) {
                const int mm = m + half * 8;
                const float vx = acc[mi][ni][half * 2 + 0];
                const float vy = acc[mi][ni][half * 2 + 1];
                if (which == 3) {
                    float2 val; val.x = vx; val.y = vy;
                    *(float2*)&g_proj[(size_t)mm * DMv + n] = val;
                } else {
                    const int b_ = mm >> 11, l_ = mm & (Lv - 1);
                    const int h_ = n >> 6,  d_ = n & (DKv - 1);
                    const __nv_bfloat16 hx = __float2bfloat16_rn(vx);
                    const __nv_bfloat16 lx = __float2bfloat16_rn(vx - __bfloat162float(hx));
                    const __nv_bfloat16 hy = __float2bfloat16_rn(vy);
                    const __nv_bfloat16 ly = __float2bfloat16_rn(vy - __bfloat162float(hy));
                    if (which == 2) {
                        const size_t base = ((size_t)(b_ * Hv + h_) * DKv + d_) * Lv + l_;
                        g_Vth[base] = hx;      g_Vtl[base] = lx;
                        g_Vth[base + Lv] = hy; g_Vtl[base + Lv] = ly;
                    } else {
                        const size_t base = ((size_t)(b_ * Hv + h_) * Lv + l_) * DKv + d_;
                        __nv_bfloat16* dh = (which == 0) ? g_Qh : g_Kh;
                        __nv_bfloat16* dl = (which == 0) ? g_Ql : g_Kl;
                        ushort2 hv; hv.x = __bfloat16_as_ushort(hx); hv.y = __bfloat16_as_ushort(hy);
                        ushort2 lv; lv.x = __bfloat16_as_ushort(lx); lv.y = __bfloat16_as_ushort(ly);
                        *(ushort2*)&dh[base] = hv;
                        *(ushort2*)&dl[base] = lv;
                    }
                }
            }
        }
    }
}

// ---------------- banded scores via HMMA: S = QK^T/8 - bias --------------------
// 128x128 tile, split-bf16 3-term MMA over d=64 (4 k-steps).
#define TS 72
__global__ void __launch_bounds__(256) scores3_kernel(float* __restrict__ attn_arg,
                                                      const int* __restrict__ ws_p)
{
    const int bh = blockIdx.z;
    const int q0 = blockIdx.y << 7;
    const int k0 = blockIdx.x << 7;
    const int hs = (*ws_p) >> 1;
    if (k0 > q0 + 127 + hs || k0 + 127 < q0 - hs) return;
    float* attn = attn_arg ? attn_arg : g_attn_fb;

    extern __shared__ __align__(16) __nv_bfloat16 smx[];   // Qh,Ql,Kh,Kl each 128*TS
    const int tid = threadIdx.x, wid = tid >> 5, lane = tid & 31;
    const uint32_t smb = smem_u32(smx);
    const uint32_t AB = 128 * TS * 2;

    {
        const __nv_bfloat16* srcs[4] = {
            g_Qh + ((size_t)bh * Lv + q0) * DKv,
            g_Ql + ((size_t)bh * Lv + q0) * DKv,
            g_Kh + ((size_t)bh * Lv + k0) * DKv,
            g_Kl + ((size_t)bh * Lv + k0) * DKv };
#pragma unroll
        for (int it = 0; it < 16; ++it) {
            const int f = tid + it * 256;       // 0..4095
            const int arr = f >> 10;
            const int u = f & 1023;
            const int row = u >> 3, c = u & 7;
            const char* src = (const char*)(srcs[arr] + (size_t)row * DKv) + c * 16;
            const uint32_t dst = smb + (uint32_t)arr * AB + (uint32_t)(row * TS + c * 8) * 2u;
            cp_async16(dst, src);
        }
        asm volatile("cp.async.commit_group;\ncp.async.wait_group 0;\n" ::: "memory");
        __syncthreads();
    }

    const int wm = (wid >> 2) * 64, wn = (wid & 3) * 32;
    float acc[4][4][4];
#pragma unroll
    for (int mi = 0; mi < 4; ++mi)
#pragma unroll
        for (int ni = 0; ni < 4; ++ni)
#pragma unroll
            for (int r = 0; r < 4; ++r) acc[mi][ni][r] = 0.f;

#pragma unroll
    for (int ks = 0; ks < 4; ++ks) {
        const int kb = ks * 16;
        uint32_t aH[4][4], aL[4][4], bH[4][2], bL[4][2];
        const uint32_t arow = (uint32_t)(((wm + (lane & 15)) * TS + kb + ((lane >> 4) << 3)) * 2);
#pragma unroll
        for (int mi = 0; mi < 4; ++mi) {
            const uint32_t ad = smb + arow + (uint32_t)(mi * 16 * TS * 2);
            LDSM_X4(aH[mi][0], aH[mi][1], aH[mi][2], aH[mi][3], ad);
            LDSM_X4(aL[mi][0], aL[mi][1], aL[mi][2], aL[mi][3], ad + AB);
        }
        const uint32_t brow = (uint32_t)((((wn + (lane & 7) + ((lane >> 4) << 3)) * TS)
                             + kb + (((lane >> 3) & 1) << 3)) * 2);
#pragma unroll
        for (int np = 0; np < 2; ++np) {
            const uint32_t bd = smb + 2u * AB + brow + (uint32_t)(np * 16 * TS * 2);
            uint32_t r0, r1, r2, r3;
            LDSM_X4(r0, r1, r2, r3, bd);
            bH[np*2][0] = r0; bH[np*2][1] = r1; bH[np*2+1][0] = r2; bH[np*2+1][1] = r3;
            LDSM_X4(r0, r1, r2, r3, bd + AB);
            bL[np*2][0] = r0; bL[np*2][1] = r1; bL[np*2+1][0] = r2; bL[np*2+1][1] = r3;
        }
#pragma unroll
        for (int mi = 0; mi < 4; ++mi)
#pragma unroll
            for (int ni = 0; ni < 4; ++ni) {
                mma_bf16(acc[mi][ni], aH[mi], bH[ni]);
                mma_bf16(acc[mi][ni], aH[mi], bL[ni]);
                mma_bf16(acc[mi][ni], aL[mi], bH[ni]);
            }
    }

    float* base = attn + (size_t)bh * Lv * Lv;
#pragma unroll
    for (int mi = 0; mi < 4; ++mi) {
#pragma unroll
        for (int half = 0; half < 2; ++half) {
            const int q = q0 + wm + mi * 16 + (lane >> 2) + half * 8;
            float* rowp = base + (size_t)q * Lv;
#pragma unroll
            for (int ni = 0; ni < 4; ++ni) {
                const int kk = k0 + wn + ni * 8 + ((lane & 3) << 1);
                const int a0 = abs(q - kk), a1 = abs(q - kk - 1);
                const float v0 = acc[mi][ni][half*2+0] * 0.125f - g_bias_lut[a0];
                const float v1 = acc[mi][ni][half*2+1] * 0.125f - g_bias_lut[a1];
                const bool i0 = a0 <= hs, i1 = a1 <= hs;
                if (i0 && i1) { float2 t; t.x = v0; t.y = v1; *(float2*)(rowp + kk) = t; }
                else if (i0) rowp[kk] = v0;
                else if (i1) rowp[kk + 1] = v1;
            }
        }
    }
}

// ---------------- row softmax; full 2048-wide row (zeros outside band) ---------
__global__ void __launch_bounds__(256) softmax_kernel(float* __restrict__ attn_arg,
    const float* __restrict__ mask, const int* __restrict__ ws_p)
{
    const int q  = blockIdx.x;
    const int bh = blockIdx.y;
    const int b  = bh >> 4;
    const int tid = threadIdx.x;
    __shared__ float buf[Lv];
    __shared__ float red[32];

    float* attn = attn_arg ? attn_arg : g_attn_fb;
    const int hs = (*ws_p) >> 1;
    const float mval = mask[b * Lv + q];
    float* row = attn + ((size_t)bh * Lv + q) * Lv;

    int lo, hi;
    if (mval != 0.f) {
        lo = q - hs; if (lo < 0) lo = 0;
        hi = q + hs; if (hi > Lv - 1) hi = Lv - 1;
        for (int c = lo + tid; c <= hi; c += 256) buf[c - lo] = row[c];
    } else {
        lo = 0; hi = Lv - 1;
        for (int c = tid; c < Lv; c += 256) buf[c] = -g_bias_lut[abs(q - c)];
    }
    __syncthreads();

    const int n = hi - lo + 1;
    float mx = -INFINITY;
    for (int i = tid; i < n; i += 256) mx = fmaxf(mx, buf[i]);
    mx = blk_reduce_max(mx, red);

    float s = 0.f;
    for (int i = tid; i < n; i += 256) { const float e = expf(buf[i] - mx); buf[i] = e; s += e; }
    s = blk_reduce_sum(s, red);
    const float inv = 1.f / s;
    __syncthreads();

    for (int c4 = tid * 4; c4 < Lv; c4 += 1024) {
        float4 v;
        v.x = (c4+0 >= lo && c4+0 <= hi) ? buf[c4+0-lo] * inv : 0.f;
        v.y = (c4+1 >= lo && c4+1 <= hi) ? buf[c4+1-lo] * inv : 0.f;
        v.z = (c4+2 >= lo && c4+2 <= hi) ? buf[c4+2-lo] * inv : 0.f;
        v.w = (c4+3 >= lo && c4+3 <= hi) ? buf[c4+3-lo] * inv : 0.f;
        *(float4*)(row + c4) = v;
    }
}

// ---------------- ctx = attn @ V via HMMA (P bf16, V split hi/lo) ---------------
// 128q x 64d tile per CTA; m-chunks of 64 over the band.
__global__ void __launch_bounds__(256) av2_kernel(const float* __restrict__ attn_arg,
    const float* __restrict__ mask, const int* __restrict__ ws_p)
{
    const int q0 = blockIdx.x << 7;
    const int bh = blockIdx.y;
    const int b = bh >> 4, h = bh & 15;
    const int hs = (*ws_p) >> 1;
    const int tid = threadIdx.x, wid = tid >> 5, lane = tid & 31;

    const float* attn = attn_arg ? attn_arg : g_attn_fb;

    extern __shared__ __align__(16) __nv_bfloat16 smy[];   // P[128*TS], Vh[64*TS], Vl[64*TS]
    const uint32_t smb = smem_u32(smy);
    const uint32_t PB = 128 * TS * 2;
    const uint32_t VB = 64 * TS * 2;

    __shared__ int s_all;
    if (tid == 0) s_all = 1;
    __syncthreads();
    if (tid < 128 && mask[b * Lv + q0 + tid] == 0.f) s_all = 0;
    __syncthreads();
    const int allm = s_all;

    const int wm = (wid >> 1) * 32, wn = (wid & 1) * 32;
    float acc[2][4][4];
#pragma unroll
    for (int mi = 0; mi < 2; ++mi)
#pragma unroll
        for (int ni = 0; ni < 4; ++ni)
#pragma unroll
            for (int r = 0; r < 4; ++r) acc[mi][ni][r] = 0.f;

    const float* abase = attn + (size_t)bh * Lv * Lv;
    const __nv_bfloat16* vh = g_Vth + (size_t)bh * DKv * Lv;
    const __nv_bfloat16* vl = g_Vtl + (size_t)bh * DKv * Lv;

    for (int m0 = 0; m0 < Lv; m0 += 64) {
        if (allm && (m0 > q0 + 127 + hs || m0 + 63 < q0 - hs)) continue;
        __syncthreads();
        // P fp32 -> bf16 smem
#pragma unroll
        for (int it = 0; it < 8; ++it) {
            const int f = tid + it * 256;   // 0..2047
            const int row = f >> 4, c4 = (f & 15) << 2;
            const float4 a = *(const float4*)(abase + (size_t)(q0 + row) * Lv + m0 + c4);
            const uint32_t p0 = ((uint32_t)__bfloat16_as_ushort(__float2bfloat16_rn(a.y)) << 16)
                              |  (uint32_t)__bfloat16_as_ushort(__float2bfloat16_rn(a.x));
            const uint32_t p1 = ((uint32_t)__bfloat16_as_ushort(__float2bfloat16_rn(a.w)) << 16)
                              |  (uint32_t)__bfloat16_as_ushort(__float2bfloat16_rn(a.z));
            uint2 pv; pv.x = p0; pv.y = p1;
            *(uint2*)((char*)smy + (size_t)(row * TS + c4) * 2) = pv;
        }
        // V tiles via cp.async
#pragma unroll
        for (int it = 0; it < 4; ++it) {
            const int f = tid + it * 256;   // 0..1023
            const int arr = f >> 9;
            const int u = f & 511;
            const int row = u >> 3, c = u & 7;
            const __nv_bfloat16* src = (arr ? vl : vh) + (size_t)row * Lv + m0 + c * 8;
            const uint32_t dst = smb + PB + (uint32_t)arr * VB + (uint32_t)(row * TS + c * 8) * 2u;
            cp_async16(dst, src);
        }
        asm volatile("cp.async.commit_group;\ncp.async.wait_group 0;\n" ::: "memory");
        __syncthreads();

#pragma unroll
        for (int ks = 0; ks < 4; ++ks) {
            const int kb = ks * 16;
            uint32_t aP[2][4], bVh[4][2], bVl[4][2];
            const uint32_t arow = (uint32_t)(((wm + (lane & 15)) * TS + kb + ((lane >> 4) << 3)) * 2);
#pragma unroll
            for (int mi = 0; mi < 2; ++mi) {
                const uint32_t ad = smb + arow + (uint32_t)(mi * 16 * TS * 2);
                LDSM_X4(aP[mi][0], aP[mi][1], aP[mi][2], aP[mi][3], ad);
            }
            const uint32_t brow = (uint32_t)((((wn + (lane & 7) + ((lane >> 4) << 3)) * TS)
                                 + kb + (((lane >> 3) & 1) << 3)) * 2);
#pragma unroll
            for (int np = 0; np < 2; ++np) {
                const uint32_t bd = smb + PB + brow + (uint32_t)(np * 16 * TS * 2);
                uint32_t r0, r1, r2, r3;
                LDSM_X4(r0, r1, r2, r3, bd);
                bVh[np*2][0] = r0; bVh[np*2][1] = r1; bVh[np*2+1][0] = r2; bVh[np*2+1][1] = r3;
                LDSM_X4(r0, r1, r2, r3, bd + VB);
                bVl[np*2][0] = r0; bVl[np*2][1] = r1; bVl[np*2+1][0] = r2; bVl[np*2+1][1] = r3;
            }
#pragma unroll
            for (int mi = 0; mi < 2; ++mi)
#pragma unroll
                for (int ni = 0; ni < 4; ++ni) {
                    mma_bf16(acc[mi][ni], aP[mi], bVh[ni]);
                    mma_bf16(acc[mi][ni], aP[mi], bVl[ni]);
                }
        }
    }

#pragma unroll
    for (int mi = 0; mi < 2; ++mi) {
#pragma unroll
        for (int half = 0; half < 2; ++half) {
            const int q = q0 + wm + mi * 16 + (lane >> 2) + half * 8;
            float* cp = g_ctx + ((size_t)b * Lv + q) * DMv + h * DKv;
#pragma unroll
            for (int ni = 0; ni < 4; ++ni) {
                const int d = wn + ni * 8 + ((lane & 3) << 1);
                float2 t;
                t.x = acc[mi][ni][half*2+0];
                t.y = acc[mi][ni][half*2+1];
                *(float2*)(cp + d) = t;
            }
        }
    }
}

// ---------------- residual + LayerNorm -----------------------------------------
__global__ void __launch_bounds__(256) ln_kernel(const float* __restrict__ qin,
    const float* __restrict__ lnw, const float* __restrict__ lnb,
    float* __restrict__ out)
{
    const int m = blockIdx.x;
    const int tid = threadIdx.x;
    __shared__ float xs[DMv];
    __shared__ float red[32];

    float s = 0.f;
    for (int i = tid; i < DMv; i += 256) {
        const float v = g_proj[(size_t)m * DMv + i] + qin[(size_t)m * DMv + i];
        xs[i] = v; s += v;
    }
    s = blk_reduce_sum(s, red);
    const float mean = s * (1.f / DMv);

    float vs = 0.f;
    for (int i = tid; i < DMv; i += 256) { const float d = xs[i] - mean; vs += d * d; }
    vs = blk_reduce_sum(vs, red);
    const float inv = rsqrtf(vs * (1.f / DMv) + 1e-6f);

    for (int i = tid; i < DMv; i += 256)
        out[(size_t)m * DMv + i] = (xs[i] - mean) * inv * lnw[i] + lnb[i];
}

// ---------------- launcher ------------------------------------------------------
extern "C" void kernel_launch(void* const* d_in, const int* in_sizes, int n_in,
                              void* d_out, int out_size)
{
    const float* q    = (const float*)d_in[0];
    const float* k    = (const float*)d_in[1];
    const float* v    = (const float*)d_in[2];
    const float* mask = (const float*)d_in[3];
    const float* Wq   = (const float*)d_in[4];
    const float* Wk   = (const float*)d_in[5];
    const float* Wv   = (const float*)d_in[6];
    const float* Wo   = (const float*)d_in[7];
    const float* scl  = (const float*)d_in[8];
    const float* tau  = (const float*)d_in[9];
    const float* lnw  = (const float*)d_in[10];
    const float* lnb  = (const float*)d_in[11];
    const int*   ws   = (const int*)d_in[12];
    (void)in_sizes; (void)n_in;

    const int gemm_smem   = 2 * 4 * TILEB;       // 81920 B
    const int scores_smem = 4 * 128 * TS * 2;    // 73728 B
    const int av_smem     = (128 + 64 + 64) * TS * 2;  // 36864 B
    cudaFuncSetAttribute(tc_gemm, cudaFuncAttributeMaxDynamicSharedMemorySize, gemm_smem);
    cudaFuncSetAttribute(scores3_kernel, cudaFuncAttributeMaxDynamicSharedMemorySize, scores_smem);
    cudaFuncSetAttribute(av2_kernel, cudaFuncAttributeMaxDynamicSharedMemorySize, av_smem);

    float* xout = (float*)d_out;
    const long long XN = (long long)Bv * Lv * DMv;
    const long long AN = (long long)BHv * Lv * Lv;
    float* attn_out = ((long long)out_size >= XN + AN) ? (xout + XN) : nullptr;

    const int A4 = Mv * DMv / 4;
    const int B4 = DMv * DMv / 4;
    const dim3 gg(DMv / 128, Mv / 128);   // (8, 32)

    bias_lut_kernel<<<8, 256>>>(scl, tau);

    split_kernel<<<A4 / 256, 256>>>(q,  0, A4, 0);
    split_kernel<<<B4 / 256, 256>>>(Wq, 1, B4, 0);
    tc_gemm<<<gg, 256, gemm_smem>>>(0);

    split_kernel<<<A4 / 256, 256>>>(k,  0, A4, 0);
    split_kernel<<<B4 / 256, 256>>>(Wk, 1, B4, 0);
    tc_gemm<<<gg, 256, gemm_smem>>>(1);

    split_kernel<<<A4 / 256, 256>>>(v,  0, A4, 0);
    split_kernel<<<B4 / 256, 256>>>(Wv, 1, B4, 0);
    tc_gemm<<<gg, 256, gemm_smem>>>(2);

    scores3_kernel<<<dim3(Lv/128, Lv/128, BHv), 256, scores_smem>>>(attn_out, ws);
    softmax_kernel<<<dim3(Lv, BHv), 256>>>(attn_out, mask, ws);
    av2_kernel<<<dim3(Lv/128, BHv), 256, av_smem>>>(attn_out, mask, ws);

    split_kernel<<<A4 / 256, 256>>>(nullptr, 0, A4, 1);   // A = g_ctx
    split_kernel<<<B4 / 256, 256>>>(Wo, 1, B4, 0);
    tc_gemm<<<gg, 256, gemm_smem>>>(3);

    ln_kernel<<<Mv, 256>>>(q, lnw, lnb, xout);
}